// round 5
// baseline (speedup 1.0000x reference)
#include <cuda_runtime.h>
#include <cuda_bf16.h>
#include <cstdint>

#define NN      8192
#define NODE    256
#define DEG     16
#define NFEAT   128
#define NHID    256
#define NCLASS  64

// ---------------- device scratch (no allocation allowed) --------------------
__device__ float    g_X[NN * NFEAT];      // adj @ x
__device__ float    g_H[NN * NHID];       // relu((adj@x) @ W1)
__device__ float    g_T[NN * NCLASS];     // g_H @ W2
__device__ unsigned g_keep[NN];           // dedup bitmask per node
__device__ float    g_W1t[NHID * NFEAT];  // W1^T  [256,128]
__device__ float    g_W2t[NCLASS * NHID]; // W2^T  [64,256]

__device__ __forceinline__ uint32_t f2tf32(float a) {
    uint32_t u; asm("cvt.rna.tf32.f32 %0, %1;" : "=r"(u) : "f"(a)); return u;
}

__device__ __forceinline__ void mma_tf32(float c[4], const uint32_t a[4], const uint32_t b[2]) {
    asm volatile(
        "mma.sync.aligned.m16n8k8.row.col.f32.tf32.tf32.f32 "
        "{%0,%1,%2,%3}, {%4,%5,%6,%7}, {%8,%9}, {%0,%1,%2,%3};"
        : "+f"(c[0]), "+f"(c[1]), "+f"(c[2]), "+f"(c[3])
        : "r"(a[0]), "r"(a[1]), "r"(a[2]), "r"(a[3]), "r"(b[0]), "r"(b[1]));
}

// ---------------------------------------------------------------------------
// prep: blocks 0..511  : agg_x (dedup'd adj @ x) — one node per HALF-warp.
//       blocks 512..543: W1^T.   blocks 544..559: W2^T.
// ---------------------------------------------------------------------------
__global__ __launch_bounds__(256)
void prep_kernel(const float* __restrict__ x, const int* __restrict__ edge,
                 const float* __restrict__ W1, const float* __restrict__ W2,
                 float* __restrict__ gX, unsigned* __restrict__ keep_out,
                 float* __restrict__ W1t, float* __restrict__ W2t)
{
    const int bid = blockIdx.x;
    const int tid = threadIdx.x;
    if (bid < 512) {
        const int node = (bid * 256 + tid) >> 4;     // one node per half-warp
        const int lane = tid & 31;
        const int hl   = tid & 15;
        const int half = (lane >> 4) & 1;
        const int base = (node >> 8) << 8;

        int e = edge[node * DEG + hl];
        // Dedup within half-warp; offset keys so halves never collide.
        int key = e + (half << 20);
        unsigned m = __match_any_sync(0xffffffffu, key);
        bool kp = (e >= 0) && ((m & ((1u << lane) - 1u)) == 0u);
        unsigned bm = __ballot_sync(0xffffffffu, kp);
        unsigned mask = (bm >> (half << 4)) & 0xffffu;
        if (hl == 0) keep_out[node] = mask;

        float4 a0 = make_float4(0.f, 0.f, 0.f, 0.f);
        float4 a1 = make_float4(0.f, 0.f, 0.f, 0.f);
#pragma unroll
        for (int t = 0; t < DEG; ++t) {
            int j = __shfl_sync(0xffffffffu, e, (lane & 16) + t);
            if (mask & (1u << t)) {
                const float* row = x + (size_t)(base + j) * NFEAT;
                float4 v0 = *reinterpret_cast<const float4*>(row + (hl << 2));
                float4 v1 = *reinterpret_cast<const float4*>(row + 64 + (hl << 2));
                a0.x += v0.x; a0.y += v0.y; a0.z += v0.z; a0.w += v0.w;
                a1.x += v1.x; a1.y += v1.y; a1.z += v1.z; a1.w += v1.w;
            }
        }
        float* dst = gX + (size_t)node * NFEAT;
        *reinterpret_cast<float4*>(dst + (hl << 2))      = a0;
        *reinterpret_cast<float4*>(dst + 64 + (hl << 2)) = a1;
    } else if (bid < 512 + 32) {
        int idx = (bid - 512) * 1024 + tid * 4;       // over 256*128
        int n = idx >> 7, k = idx & 127;
        float4 v;
        v.x = W1[(k + 0) * NHID + n]; v.y = W1[(k + 1) * NHID + n];
        v.z = W1[(k + 2) * NHID + n]; v.w = W1[(k + 3) * NHID + n];
        *reinterpret_cast<float4*>(W1t + idx) = v;
    } else {
        int idx = (bid - 544) * 1024 + tid * 4;       // over 64*256
        int n = idx >> 8, k = idx & 255;
        float4 v;
        v.x = W2[(k + 0) * NCLASS + n]; v.y = W2[(k + 1) * NCLASS + n];
        v.z = W2[(k + 2) * NCLASS + n]; v.w = W2[(k + 3) * NCLASS + n];
        *reinterpret_cast<float4*>(W2t + idx) = v;
    }
}

// ---------------------------------------------------------------------------
// Warp-level tf32 mma.sync GEMM with 3xTF32 compensation.
// C[BM x BN per CTA] = A[M,K] @ Bt[N,K]^T. 256 threads = 8 warps.
// ---------------------------------------------------------------------------
template<int BM, int BN, int KTOT, int WM, int WN, bool RELU>
__global__ __launch_bounds__(256, 2)
void gemm_mma(const float* __restrict__ A, const float* __restrict__ Bt,
              float* __restrict__ C, int ldc)
{
    constexpr int LDS_   = 36;                // 32 k + 4 pad
    constexpr int NWN    = BN / WN;
    constexpr int MSUB   = WM / 16;
    constexpr int NSUB   = WN / 8;
    constexpr int NCHUNK = KTOT / 32;
    constexpr int A_FLT  = BM * LDS_;
    constexpr int B_FLT  = BN * LDS_;

    extern __shared__ float sm[];
    float* Ah = sm;
    float* Al = Ah + A_FLT;
    float* Bh = Al + A_FLT;
    float* Bl = Bh + B_FLT;

    const int tid   = threadIdx.x;
    const int wid   = tid >> 5;
    const int lane  = tid & 31;
    const int brow  = blockIdx.x * BM;
    const int bcol  = blockIdx.y * BN;
    const int warpM = (wid / NWN) * WM;
    const int warpN = (wid % NWN) * WN;
    const int grp   = lane >> 2;
    const int qk    = lane & 3;

    float acc[MSUB][NSUB][4] = {};

    for (int c = 0; c < NCHUNK; ++c) {
#pragma unroll
        for (int i = tid; i < BM * 8; i += 256) {
            int r = i >> 3, f = (i & 7) << 2;
            float4 v = *reinterpret_cast<const float4*>(
                A + (size_t)(brow + r) * KTOT + c * 32 + f);
            float* ph = Ah + r * LDS_ + f;
            float* pl = Al + r * LDS_ + f;
            float hx = __uint_as_float(f2tf32(v.x));
            float hy = __uint_as_float(f2tf32(v.y));
            float hz = __uint_as_float(f2tf32(v.z));
            float hw = __uint_as_float(f2tf32(v.w));
            ph[0] = hx; ph[1] = hy; ph[2] = hz; ph[3] = hw;
            pl[0] = __uint_as_float(f2tf32(v.x - hx));
            pl[1] = __uint_as_float(f2tf32(v.y - hy));
            pl[2] = __uint_as_float(f2tf32(v.z - hz));
            pl[3] = __uint_as_float(f2tf32(v.w - hw));
        }
#pragma unroll
        for (int i = tid; i < BN * 8; i += 256) {
            int r = i >> 3, f = (i & 7) << 2;
            float4 v = *reinterpret_cast<const float4*>(
                Bt + (size_t)(bcol + r) * KTOT + c * 32 + f);
            float* ph = Bh + r * LDS_ + f;
            float* pl = Bl + r * LDS_ + f;
            float hx = __uint_as_float(f2tf32(v.x));
            float hy = __uint_as_float(f2tf32(v.y));
            float hz = __uint_as_float(f2tf32(v.z));
            float hw = __uint_as_float(f2tf32(v.w));
            ph[0] = hx; ph[1] = hy; ph[2] = hz; ph[3] = hw;
            pl[0] = __uint_as_float(f2tf32(v.x - hx));
            pl[1] = __uint_as_float(f2tf32(v.y - hy));
            pl[2] = __uint_as_float(f2tf32(v.z - hz));
            pl[3] = __uint_as_float(f2tf32(v.w - hw));
        }
        __syncthreads();

#pragma unroll
        for (int ks = 0; ks < 4; ++ks) {
            const int kb = ks * 8;
            uint32_t afh[MSUB][4], afl[MSUB][4];
#pragma unroll
            for (int ms = 0; ms < MSUB; ++ms) {
                int r0 = (warpM + ms * 16 + grp) * LDS_ + kb + qk;
                int r1 = r0 + 8 * LDS_;
                afh[ms][0] = __float_as_uint(Ah[r0]);
                afh[ms][1] = __float_as_uint(Ah[r1]);
                afh[ms][2] = __float_as_uint(Ah[r0 + 4]);
                afh[ms][3] = __float_as_uint(Ah[r1 + 4]);
                afl[ms][0] = __float_as_uint(Al[r0]);
                afl[ms][1] = __float_as_uint(Al[r1]);
                afl[ms][2] = __float_as_uint(Al[r0 + 4]);
                afl[ms][3] = __float_as_uint(Al[r1 + 4]);
            }
            uint32_t bfh[NSUB][2], bfl[NSUB][2];
#pragma unroll
            for (int ns = 0; ns < NSUB; ++ns) {
                int b0 = (warpN + ns * 8 + grp) * LDS_ + kb + qk;
                bfh[ns][0] = __float_as_uint(Bh[b0]);
                bfh[ns][1] = __float_as_uint(Bh[b0 + 4]);
                bfl[ns][0] = __float_as_uint(Bl[b0]);
                bfl[ns][1] = __float_as_uint(Bl[b0 + 4]);
            }
#pragma unroll
            for (int ms = 0; ms < MSUB; ++ms)
#pragma unroll
                for (int ns = 0; ns < NSUB; ++ns) {
                    mma_tf32(acc[ms][ns], afh[ms], bfh[ns]);
                    mma_tf32(acc[ms][ns], afh[ms], bfl[ns]);
                    mma_tf32(acc[ms][ns], afl[ms], bfh[ns]);
                }
        }
        __syncthreads();
    }

#pragma unroll
    for (int ms = 0; ms < MSUB; ++ms) {
#pragma unroll
        for (int ns = 0; ns < NSUB; ++ns) {
            int row = brow + warpM + ms * 16 + grp;
            int col = bcol + warpN + ns * 8 + 2 * qk;
            float2 v0 = make_float2(acc[ms][ns][0], acc[ms][ns][1]);
            float2 v1 = make_float2(acc[ms][ns][2], acc[ms][ns][3]);
            if (RELU) {
                v0.x = fmaxf(v0.x, 0.f); v0.y = fmaxf(v0.y, 0.f);
                v1.x = fmaxf(v1.x, 0.f); v1.y = fmaxf(v1.y, 0.f);
            }
            *reinterpret_cast<float2*>(C + (size_t)row * ldc + col)       = v0;
            *reinterpret_cast<float2*>(C + (size_t)(row + 8) * ldc + col) = v1;
        }
    }
}

// ---------------------------------------------------------------------------
// Layer-2 aggregation + log_softmax. One node per HALF-warp, float4 per lane.
// ---------------------------------------------------------------------------
__global__ __launch_bounds__(256)
void agg_lsm_kernel(const float* __restrict__ T, const int* __restrict__ edge,
                    const unsigned* __restrict__ keep_in, float* __restrict__ out)
{
    const int node = (blockIdx.x * blockDim.x + threadIdx.x) >> 4;
    const int lane = threadIdx.x & 31;
    const int hl   = threadIdx.x & 15;
    const int base = (node >> 8) << 8;

    int e = edge[node * DEG + hl];
    unsigned mask = keep_in[node];

    float4 a = make_float4(0.f, 0.f, 0.f, 0.f);
#pragma unroll
    for (int t = 0; t < DEG; ++t) {
        int j = __shfl_sync(0xffffffffu, e, (lane & 16) + t);
        if (mask & (1u << t)) {
            float4 v = *reinterpret_cast<const float4*>(
                T + (size_t)(base + j) * NCLASS + (hl << 2));
            a.x += v.x; a.y += v.y; a.z += v.z; a.w += v.w;
        }
    }

    // log_softmax over this half-warp's 64 values
    float mx = fmaxf(fmaxf(a.x, a.y), fmaxf(a.z, a.w));
#pragma unroll
    for (int o = 8; o; o >>= 1)
        mx = fmaxf(mx, __shfl_xor_sync(0xffffffffu, mx, o));
    float s = expf(a.x - mx) + expf(a.y - mx) + expf(a.z - mx) + expf(a.w - mx);
#pragma unroll
    for (int o = 8; o; o >>= 1)
        s += __shfl_xor_sync(0xffffffffu, s, o);
    float lse = logf(s) + mx;

    float4 r = make_float4(a.x - lse, a.y - lse, a.z - lse, a.w - lse);
    *reinterpret_cast<float4*>(out + (size_t)node * NCLASS + (hl << 2)) = r;
}

// ---------------------------------------------------------------------------
extern "C" void kernel_launch(void* const* d_in, const int* in_sizes, int n_in,
                              void* d_out, int out_size)
{
    const float* x    = (const float*)d_in[0];
    const int*   edge = (const int*)  d_in[1];
    const float* W1   = (const float*)d_in[2];
    const float* W2   = (const float*)d_in[3];
    float* out = (float*)d_out;

    float *gX, *gH, *gT, *gW1t, *gW2t;
    unsigned *gK;
    cudaGetSymbolAddress((void**)&gX,   g_X);
    cudaGetSymbolAddress((void**)&gH,   g_H);
    cudaGetSymbolAddress((void**)&gT,   g_T);
    cudaGetSymbolAddress((void**)&gK,   g_keep);
    cudaGetSymbolAddress((void**)&gW1t, g_W1t);
    cudaGetSymbolAddress((void**)&gW2t, g_W2t);

    // GEMM1: BM=128,BN=64,K=128, warp 32x32 -> grid (64,4), smem 55296B, 2 CTA/SM
    // GEMM2: BM=32, BN=64,K=256, warp 16x16 -> grid (256,1), smem 27648B
    constexpr int SMEM1 = (128 + 64) * 36 * 4 * 2;
    constexpr int SMEM2 = (32 + 64) * 36 * 4 * 2;
    cudaFuncSetAttribute(gemm_mma<128, 64, 128, 32, 32, true>,
                         cudaFuncAttributeMaxDynamicSharedMemorySize, SMEM1);
    cudaFuncSetAttribute(gemm_mma<32, 64, 256, 16, 16, false>,
                         cudaFuncAttributeMaxDynamicSharedMemorySize, SMEM2);

    prep_kernel<<<560, 256>>>(x, edge, W1, W2, gX, gK, gW1t, gW2t);
    gemm_mma<128, 64, 128, 32, 32, true>
        <<<dim3(64, 4), 256, SMEM1>>>(gX, gW1t, gH, NHID);
    gemm_mma<32, 64, 256, 16, 16, false>
        <<<dim3(256, 1), 256, SMEM2>>>(gH, gW2t, gT, NCLASS);
    agg_lsm_kernel<<<NN / 16, 256>>>(gT, edge, gK, out);
}